// round 1
// baseline (speedup 1.0000x reference)
#include <cuda_runtime.h>
#include <math.h>
#include <stdint.h>

// ---------------- problem constants ----------------
#define S_LEN   2048
#define BATCH   2
#define M_ROWS  4096            // BATCH * S_LEN
#define DIM_    2048
#define QL      1536            // Q_LORA
#define NH_     16
#define QK_     192             // NOPE + ROPE
#define NOPE_   128
#define ROPE_D  64
#define VDIM_   128
#define KVL     512             // KV_LORA
#define KVD_    576             // KVL + ROPE
#define NQK     (NH_*QK_)       // 3072
#define NKV     (NH_*(NOPE_+VDIM_)) // 4096
#define EPS_    1.1920929e-07f

// ---------------- scratch (static device globals; no allocs) ----------------
__device__ float g_qmid [(size_t)M_ROWS * QL];
__device__ float g_qlat [(size_t)M_ROWS * QL];
__device__ float g_Q    [(size_t)M_ROWS * NQK];
__device__ float g_kvd  [(size_t)M_ROWS * KVD_];
__device__ float g_kvlat[(size_t)M_ROWS * KVL];
__device__ float g_KV   [(size_t)M_ROWS * NKV];
__device__ float g_Krope[(size_t)M_ROWS * ROPE_D];
__device__ float g_Kfull[(size_t)M_ROWS * NQK];
__device__ float g_scores[(size_t)BATCH * NH_ * S_LEN * S_LEN]; // 536 MB
__device__ float g_O    [(size_t)M_ROWS * (NH_*VDIM_)];

// ---------------- GEMM: C[M,N] = A[M,K] * op(B) + bias ----------------
// NT=true : B is [N,K] row-major.  NT=false: B is [K,N] row-major.
// CSKIP   : skip blocks fully above causal diagonal (scores GEMM).
// CK      : truncate K loop at m0+BM (PV GEMM; masked probs are exactly 0).
// Batched over blockIdx.z: pointers offset by (z/NH)*x1 + (z%NH)*x2.
#define BM 128
#define BN 128
#define BK 16

template<bool NT, bool CSKIP, bool CK>
__global__ void __launch_bounds__(256, 2)
gemm_kernel(const float* __restrict__ A, const float* __restrict__ B,
            const float* __restrict__ bias, float* __restrict__ C,
            int M, int N, int K, int lda, int ldb, int ldc,
            long long a1, long long a2, long long b1, long long b2,
            long long c1, long long c2)
{
    __shared__ float As[BK][BM];
    __shared__ float Bs[BK][BN];

    const int z  = blockIdx.z;
    const int zb = z / NH_, zh = z % NH_;
    A += (long long)zb * a1 + (long long)zh * a2;
    B += (long long)zb * b1 + (long long)zh * b2;
    C += (long long)zb * c1 + (long long)zh * c2;

    const int tid = threadIdx.x;
    const int tx = tid & 15, ty = tid >> 4;
    const int m0 = blockIdx.y * BM;
    const int n0 = blockIdx.x * BN;

    if (CSKIP && n0 >= m0 + BM) return;   // fully masked score tile

    int Kend = K;
    if (CK) { int ke = m0 + BM; Kend = (ke < K) ? ke : K; }

    unsigned long long acc[8][4];
    #pragma unroll
    for (int i = 0; i < 8; i++)
        #pragma unroll
        for (int j = 0; j < 4; j++) acc[i][j] = 0ull;

    const int ar = tid >> 2;           // 0..63
    const int ak = (tid & 3) * 4;      // 0,4,8,12

    for (int k0 = 0; k0 < Kend; k0 += BK) {
        #pragma unroll
        for (int r = 0; r < 2; r++) {
            int row = ar + r * 64;
            float4 v = *reinterpret_cast<const float4*>(
                A + (long long)(m0 + row) * lda + k0 + ak);
            As[ak+0][row] = v.x; As[ak+1][row] = v.y;
            As[ak+2][row] = v.z; As[ak+3][row] = v.w;
        }
        if (NT) {
            #pragma unroll
            for (int r = 0; r < 2; r++) {
                int row = ar + r * 64;     // n index
                float4 v = make_float4(0.f, 0.f, 0.f, 0.f);
                if (n0 + row < N)
                    v = *reinterpret_cast<const float4*>(
                        B + (long long)(n0 + row) * ldb + k0 + ak);
                Bs[ak+0][row] = v.x; Bs[ak+1][row] = v.y;
                Bs[ak+2][row] = v.z; Bs[ak+3][row] = v.w;
            }
        } else {
            #pragma unroll
            for (int r = 0; r < 2; r++) {
                int idx = tid + r * 256;       // 0..511
                int kk = idx >> 5;             // 0..15
                int nc = (idx & 31) * 4;       // 0..124
                float4 v = make_float4(0.f, 0.f, 0.f, 0.f);
                if (n0 + nc < N)
                    v = *reinterpret_cast<const float4*>(
                        B + (long long)(k0 + kk) * ldb + n0 + nc);
                *reinterpret_cast<float4*>(&Bs[kk][nc]) = v;
            }
        }
        __syncthreads();

        #pragma unroll
        for (int kk = 0; kk < BK; kk++) {
            union { float4 v[2]; float f[8]; } au;
            union { float4 v[2]; unsigned long long u[4]; } bu;
            au.v[0] = *reinterpret_cast<const float4*>(&As[kk][ty*8]);
            au.v[1] = *reinterpret_cast<const float4*>(&As[kk][ty*8+4]);
            bu.v[0] = *reinterpret_cast<const float4*>(&Bs[kk][tx*8]);
            bu.v[1] = *reinterpret_cast<const float4*>(&Bs[kk][tx*8+4]);
            #pragma unroll
            for (int i = 0; i < 8; i++) {
                unsigned long long a2r;
                asm("mov.b64 %0, {%1, %1};" : "=l"(a2r) : "f"(au.f[i]));
                #pragma unroll
                for (int j = 0; j < 4; j++)
                    asm("fma.rn.f32x2 %0, %1, %2, %0;"
                        : "+l"(acc[i][j]) : "l"(a2r), "l"(bu.u[j]));
            }
        }
        __syncthreads();
    }

    #pragma unroll
    for (int i = 0; i < 8; i++) {
        long long m = m0 + ty * 8 + i;
        #pragma unroll
        for (int j = 0; j < 4; j++) {
            union { unsigned long long u; float2 f; } cu; cu.u = acc[i][j];
            int n = n0 + tx * 8 + 2 * j;
            if (n < N) {
                float v = cu.f.x; if (bias) v += bias[n];
                C[m * ldc + n] = v;
            }
            if (n + 1 < N) {
                float v = cu.f.y; if (bias) v += bias[n + 1];
                C[m * ldc + n + 1] = v;
            }
        }
    }
}

// ---------------- RMSNorm (row-wise) ----------------
__global__ void __launch_bounds__(256)
rmsnorm_kernel(const float* __restrict__ in, const float* __restrict__ w,
               float* __restrict__ out, int n, int ldin, int ldout)
{
    long long row = blockIdx.x;
    const float* p = in + row * ldin;
    float s = 0.f;
    for (int i = threadIdx.x; i < n; i += 256) { float v = p[i]; s += v * v; }
    __shared__ float red[256];
    red[threadIdx.x] = s; __syncthreads();
    for (int st = 128; st > 0; st >>= 1) {
        if (threadIdx.x < st) red[threadIdx.x] += red[threadIdx.x + st];
        __syncthreads();
    }
    float scale = rsqrtf(red[0] / (float)n + EPS_);
    for (int i = threadIdx.x; i < n; i += 256)
        out[row * ldout + i] = p[i] * scale * w[i];
}

// ---------------- RoPE on Q (in place, dims 128..191 of each head) ----------
__global__ void __launch_bounds__(256)
rope_q_kernel(float* __restrict__ Q, const float* __restrict__ freqs)
{
    int idx = blockIdx.x * 256 + threadIdx.x;
    const int total = M_ROWS * NH_ * (ROPE_D / 2);
    if (idx >= total) return;
    int d = idx % (ROPE_D / 2);
    int h = (idx / (ROPE_D / 2)) % NH_;
    int m = idx / ((ROPE_D / 2) * NH_);
    int s = m % S_LEN;
    float f = freqs[s * (ROPE_D / 2) + d];
    float c = cosf(f), sn = sinf(f);
    float* p = Q + (long long)m * NQK + h * QK_ + NOPE_ + 2 * d;
    float x0 = p[0], x1 = p[1];
    p[0] = x0 * c - x1 * sn;
    p[1] = x0 * sn + x1 * c;
}

// ---------------- RoPE on K_rope (kvd cols 512..575 -> Krope) ---------------
__global__ void __launch_bounds__(256)
rope_k_kernel(const float* __restrict__ kvd, float* __restrict__ Krope,
              const float* __restrict__ freqs)
{
    int idx = blockIdx.x * 256 + threadIdx.x;
    const int total = M_ROWS * (ROPE_D / 2);
    if (idx >= total) return;
    int d = idx % (ROPE_D / 2);
    int m = idx / (ROPE_D / 2);
    int s = m % S_LEN;
    float f = freqs[s * (ROPE_D / 2) + d];
    float c = cosf(f), sn = sinf(f);
    const float* p = kvd + (long long)m * KVD_ + KVL + 2 * d;
    float x0 = p[0], x1 = p[1];
    Krope[(long long)m * ROPE_D + 2 * d]     = x0 * c - x1 * sn;
    Krope[(long long)m * ROPE_D + 2 * d + 1] = x0 * sn + x1 * c;
}

// ---------------- assemble K = concat(K_nope, K_rope bcast) -----------------
__global__ void __launch_bounds__(256)
kfull_kernel(const float* __restrict__ KV, const float* __restrict__ Krope,
             float* __restrict__ Kfull)
{
    long long idx = (long long)blockIdx.x * 256 + threadIdx.x;
    const long long total = (long long)M_ROWS * NQK;
    if (idx >= total) return;
    int r = (int)(idx % NQK);
    long long m = idx / NQK;
    int h = r / QK_, d = r % QK_;
    float v = (d < NOPE_) ? KV[m * NKV + h * (NOPE_+VDIM_) + d]
                          : Krope[m * ROPE_D + (d - NOPE_)];
    Kfull[idx] = v;
}

// ---------------- softmax over key axis (scale + mask fused) ----------------
__global__ void __launch_bounds__(256)
softmax_kernel(float* __restrict__ scores, const float* __restrict__ mask,
               float scale)
{
    long long row = blockIdx.x;                 // z*S + q
    int q = (int)(row % S_LEN);
    float* p = scores + row * S_LEN;
    const float* mk = mask + (long long)q * S_LEN;
    float vals[8];
    float mx = -3.4e38f;
    #pragma unroll
    for (int j = 0; j < 8; j++) {
        int k = threadIdx.x + j * 256;
        float v = p[k] * scale + mk[k];
        vals[j] = v; mx = fmaxf(mx, v);
    }
    __shared__ float red[256];
    red[threadIdx.x] = mx; __syncthreads();
    for (int st = 128; st > 0; st >>= 1) {
        if (threadIdx.x < st)
            red[threadIdx.x] = fmaxf(red[threadIdx.x], red[threadIdx.x + st]);
        __syncthreads();
    }
    mx = red[0]; __syncthreads();
    float sum = 0.f;
    #pragma unroll
    for (int j = 0; j < 8; j++) { vals[j] = expf(vals[j] - mx); sum += vals[j]; }
    red[threadIdx.x] = sum; __syncthreads();
    for (int st = 128; st > 0; st >>= 1) {
        if (threadIdx.x < st) red[threadIdx.x] += red[threadIdx.x + st];
        __syncthreads();
    }
    float inv = 1.f / red[0];
    #pragma unroll
    for (int j = 0; j < 8; j++) {
        int k = threadIdx.x + j * 256;
        p[k] = vals[j] * inv;
    }
}

// ---------------- host side ----------------
extern "C" void kernel_launch(void* const* d_in, const int* in_sizes, int n_in,
                              void* d_out, int out_size)
{
    (void)in_sizes; (void)n_in; (void)out_size;
    const float* x        = (const float*)d_in[0];
    const float* freqs    = (const float*)d_in[1];
    const float* mask     = (const float*)d_in[2];
    const float* Wq_down  = (const float*)d_in[3];
    const float* bq_down  = (const float*)d_in[4];
    const float* q_norm   = (const float*)d_in[5];
    const float* Wq_up    = (const float*)d_in[6];
    const float* bq_up    = (const float*)d_in[7];
    const float* Wkv_down = (const float*)d_in[8];
    const float* bkv_down = (const float*)d_in[9];
    const float* kv_norm  = (const float*)d_in[10];
    const float* Wkv_up   = (const float*)d_in[11];
    const float* bkv_up   = (const float*)d_in[12];
    const float* Wo       = (const float*)d_in[13];
    const float* bo       = (const float*)d_in[14];
    float* out = (float*)d_out;

    void* p;
    cudaGetSymbolAddress(&p, g_qmid);   float* qmid  = (float*)p;
    cudaGetSymbolAddress(&p, g_qlat);   float* qlat  = (float*)p;
    cudaGetSymbolAddress(&p, g_Q);      float* Qb    = (float*)p;
    cudaGetSymbolAddress(&p, g_kvd);    float* kvd   = (float*)p;
    cudaGetSymbolAddress(&p, g_kvlat);  float* kvlat = (float*)p;
    cudaGetSymbolAddress(&p, g_KV);     float* KVb   = (float*)p;
    cudaGetSymbolAddress(&p, g_Krope);  float* Krope = (float*)p;
    cudaGetSymbolAddress(&p, g_Kfull);  float* Kfull = (float*)p;
    cudaGetSymbolAddress(&p, g_scores); float* scr   = (float*)p;
    cudaGetSymbolAddress(&p, g_O);      float* Ob    = (float*)p;

    const float scale = 1.0f / sqrtf((float)QK_);
    const long long Z0 = 0;

    // 1) q_mid = x @ Wq_down^T + b
    gemm_kernel<true,false,false><<<dim3(QL/128, M_ROWS/128, 1), 256>>>(
        x, Wq_down, bq_down, qmid, M_ROWS, QL, DIM_, DIM_, DIM_, QL,
        Z0,Z0,Z0,Z0,Z0,Z0);
    // 2) q_lat = rmsnorm(q_mid)
    rmsnorm_kernel<<<M_ROWS, 256>>>(qmid, q_norm, qlat, QL, QL, QL);
    // 3) Q = q_lat @ Wq_up^T + b
    gemm_kernel<true,false,false><<<dim3(NQK/128, M_ROWS/128, 1), 256>>>(
        qlat, Wq_up, bq_up, Qb, M_ROWS, NQK, QL, QL, QL, NQK,
        Z0,Z0,Z0,Z0,Z0,Z0);
    // 4) RoPE(Q)
    rope_q_kernel<<<(M_ROWS*NH_*(ROPE_D/2) + 255)/256, 256>>>(Qb, freqs);
    // 5) kvd = x @ Wkv_down^T + b
    gemm_kernel<true,false,false><<<dim3((KVD_+127)/128, M_ROWS/128, 1), 256>>>(
        x, Wkv_down, bkv_down, kvd, M_ROWS, KVD_, DIM_, DIM_, DIM_, KVD_,
        Z0,Z0,Z0,Z0,Z0,Z0);
    // 6) kv_lat = rmsnorm(kvd[:, :512]); Krope = rope(kvd[:, 512:])
    rmsnorm_kernel<<<M_ROWS, 256>>>(kvd, kv_norm, kvlat, KVL, KVD_, KVL);
    rope_k_kernel<<<(M_ROWS*(ROPE_D/2) + 255)/256, 256>>>(kvd, Krope, freqs);
    // 7) KV = kv_lat @ Wkv_up^T + b   -> [m, h, (K_nope|V)]
    gemm_kernel<true,false,false><<<dim3(NKV/128, M_ROWS/128, 1), 256>>>(
        kvlat, Wkv_up, bkv_up, KVb, M_ROWS, NKV, KVL, KVL, KVL, NKV,
        Z0,Z0,Z0,Z0,Z0,Z0);
    // 8) Kfull = concat(K_nope, Krope broadcast)
    kfull_kernel<<<(int)(((long long)M_ROWS*NQK + 255)/256), 256>>>(KVb, Krope, Kfull);

    // 9) scores[z] = Q_bh @ Kfull_bh^T   (batched z = b*NH + h, causal skip)
    gemm_kernel<true,true,false><<<dim3(S_LEN/128, S_LEN/128, BATCH*NH_), 256>>>(
        Qb, Kfull, nullptr, scr, S_LEN, S_LEN, QK_, NQK, NQK, S_LEN,
        (long long)S_LEN*NQK, (long long)QK_,
        (long long)S_LEN*NQK, (long long)QK_,
        (long long)NH_*S_LEN*S_LEN, (long long)S_LEN*S_LEN);

    // 10) softmax rows (scale + causal mask)
    softmax_kernel<<<BATCH*NH_*S_LEN, 256>>>(scr, mask, scale);

    // 11) O_bh = attn_bh @ V_bh   (NN, causal K truncation; V at +NOPE_ offset)
    gemm_kernel<false,false,true><<<dim3(1, S_LEN/128, BATCH*NH_), 256>>>(
        scr, KVb + NOPE_, nullptr, Ob, S_LEN, VDIM_, S_LEN, S_LEN, NKV, NH_*VDIM_,
        (long long)NH_*S_LEN*S_LEN, (long long)S_LEN*S_LEN,
        (long long)S_LEN*NKV, (long long)(NOPE_+VDIM_),
        (long long)S_LEN*(NH_*VDIM_), (long long)VDIM_);

    // 12) out = O @ Wo^T + b
    gemm_kernel<true,false,false><<<dim3(DIM_/128, M_ROWS/128, 1), 256>>>(
        Ob, Wo, bo, out, M_ROWS, DIM_, NH_*VDIM_, NH_*VDIM_, NH_*VDIM_, DIM_,
        Z0,Z0,Z0,Z0,Z0,Z0);
}

// round 3
// speedup vs baseline: 2.1378x; 2.1378x over previous
#include <cuda_runtime.h>
#include <cuda_bf16.h>
#include <math.h>
#include <stdint.h>

typedef __nv_bfloat16 bf16;

// ---------------- problem constants ----------------
#define S_LEN   2048
#define BATCH   2
#define M_ROWS  4096
#define DIM_    2048
#define QL      1536
#define NH_     16
#define QK_     192
#define NOPE_   128
#define ROPE_D  64
#define VDIM_   128
#define KVL     512
#define KVD_    576
#define NQK     (NH_*QK_)            // 3072
#define NKV     (NH_*(NOPE_+VDIM_))  // 4096
#define EPS_    1.1920929e-07f
#define PITCH   24                   // smem row pitch in bf16 (48B, LDSM conflict-free)

// ---------------- scratch ----------------
__device__ float g_qmid [(size_t)M_ROWS * QL];
__device__ float g_qlat [(size_t)M_ROWS * QL];
__device__ float g_Q    [(size_t)M_ROWS * NQK];
__device__ float g_kvd  [(size_t)M_ROWS * KVD_];
__device__ float g_kvlat[(size_t)M_ROWS * KVL];
__device__ float g_KV   [(size_t)M_ROWS * NKV];
__device__ float g_Krope[(size_t)M_ROWS * ROPE_D];
__device__ float g_Kfull[(size_t)M_ROWS * NQK];
__device__ float g_scores[(size_t)BATCH * NH_ * S_LEN * S_LEN];
__device__ float g_O    [(size_t)M_ROWS * (NH_*VDIM_)];

// split bf16 buffers (hi / lo)
__device__ bf16 g_xh [(size_t)M_ROWS*DIM_],  g_xl [(size_t)M_ROWS*DIM_];
__device__ bf16 g_qlh[(size_t)M_ROWS*QL],    g_qll[(size_t)M_ROWS*QL];
__device__ bf16 g_Qh [(size_t)M_ROWS*NQK],   g_Ql [(size_t)M_ROWS*NQK];
__device__ bf16 g_klh[(size_t)M_ROWS*KVL],   g_kll[(size_t)M_ROWS*KVL];
__device__ bf16 g_Kfh[(size_t)M_ROWS*NQK],   g_Kfl[(size_t)M_ROWS*NQK];
__device__ bf16 g_Vth[(size_t)BATCH*NH_*VDIM_*S_LEN], g_Vtl[(size_t)BATCH*NH_*VDIM_*S_LEN];
__device__ bf16 g_ph [(size_t)BATCH*NH_*S_LEN*S_LEN], g_pl [(size_t)BATCH*NH_*S_LEN*S_LEN];
__device__ bf16 g_Oh [(size_t)M_ROWS*DIM_], g_Ol [(size_t)M_ROWS*DIM_];
// weight splits
__device__ bf16 g_Wqdh[(size_t)QL*DIM_],   g_Wqdl[(size_t)QL*DIM_];
__device__ bf16 g_Wquh[(size_t)NQK*QL],    g_Wqul[(size_t)NQK*QL];
__device__ bf16 g_Wkdh[(size_t)KVD_*DIM_], g_Wkdl[(size_t)KVD_*DIM_];
__device__ bf16 g_Wkuh[(size_t)NKV*KVL],   g_Wkul[(size_t)NKV*KVL];
__device__ bf16 g_Woh [(size_t)DIM_*DIM_], g_Wol [(size_t)DIM_*DIM_];

// ---------------- PTX helpers ----------------
__device__ __forceinline__ void cp_async16(uint32_t saddr, const void* g, int sz) {
    asm volatile("cp.async.ca.shared.global [%0], [%1], 16, %2;\n"
                 :: "r"(saddr), "l"(g), "r"(sz));
}
__device__ __forceinline__ void cp_commit() { asm volatile("cp.async.commit_group;\n"); }
template<int N> __device__ __forceinline__ void cp_wait() {
    asm volatile("cp.async.wait_group %0;\n" :: "n"(N));
}
__device__ __forceinline__ void ldsm4(uint32_t a[4], uint32_t addr) {
    asm volatile("ldmatrix.sync.aligned.m8n8.x4.shared.b16 {%0,%1,%2,%3}, [%4];\n"
                 : "=r"(a[0]), "=r"(a[1]), "=r"(a[2]), "=r"(a[3]) : "r"(addr));
}
// B tile is stored [n][k] in smem == mma.row.col B operand layout: NO trans.
__device__ __forceinline__ void ldsm2(uint32_t b[2], uint32_t addr) {
    asm volatile("ldmatrix.sync.aligned.m8n8.x2.shared.b16 {%0,%1}, [%2];\n"
                 : "=r"(b[0]), "=r"(b[1]) : "r"(addr));
}
__device__ __forceinline__ void mma16816(float c[4], const uint32_t a[4], const uint32_t b[2]) {
    asm volatile(
        "mma.sync.aligned.m16n8k16.row.col.f32.bf16.bf16.f32 "
        "{%0,%1,%2,%3}, {%4,%5,%6,%7}, {%8,%9}, {%0,%1,%2,%3};\n"
        : "+f"(c[0]), "+f"(c[1]), "+f"(c[2]), "+f"(c[3])
        : "r"(a[0]), "r"(a[1]), "r"(a[2]), "r"(a[3]), "r"(b[0]), "r"(b[1]));
}

// ---------------- split-bf16 tensor-core GEMM ----------------
// C[M,N] = (Ah+Al)[M,K] * (Bh+Bl)[N,K]^T + bias   (hi*hi + hi*lo + lo*hi)
// CSKIP: skip tiles above causal diagonal. CK: truncate K at m0+128.
// Batched over blockIdx.z = zb*NH + zh with element offsets.
template<bool CSKIP, bool CK>
__global__ void __launch_bounds__(256)
mma_gemm(const bf16* __restrict__ Ah, const bf16* __restrict__ Al,
         const bf16* __restrict__ Bh, const bf16* __restrict__ Bl,
         const float* __restrict__ bias, float* __restrict__ C,
         int M, int N, int K, int lda, int ldb, int ldc,
         long long a1, long long a2, long long b1, long long b2,
         long long c1, long long c2)
{
    __shared__ bf16 sm[2][4][128][PITCH];   // [stage][Ah,Al,Bh,Bl][row][col]

    const int z = blockIdx.z, zb = z / NH_, zh = z % NH_;
    const long long ao = (long long)zb*a1 + (long long)zh*a2;
    const long long bo2 = (long long)zb*b1 + (long long)zh*b2;
    Ah += ao; Al += ao; Bh += bo2; Bl += bo2;
    C  += (long long)zb*c1 + (long long)zh*c2;

    const int m0 = blockIdx.y * 128, n0 = blockIdx.x * 128;
    if (CSKIP && n0 >= m0 + 128) return;
    int Kend = K;
    if (CK) { int ke = m0 + 128; if (ke < K) Kend = ke; }
    const int nk = Kend >> 4;

    const int tid = threadIdx.x, lane = tid & 31, warp = tid >> 5;
    const int wm = (warp >> 2) * 64, wn = (warp & 3) * 32;
    const int lr = tid >> 1, seg = tid & 1;
    const uint32_t smbase = (uint32_t)__cvta_generic_to_shared(&sm[0][0][0][0]);

    float acc[4][4][4];
    #pragma unroll
    for (int i = 0; i < 4; i++)
        #pragma unroll
        for (int j = 0; j < 4; j++)
            #pragma unroll
            for (int r = 0; r < 4; r++) acc[i][j][r] = 0.f;

    auto issue = [&](int st, int k0) {
        const bf16* ga0 = Ah + (size_t)(m0 + lr) * lda + k0 + seg * 8;
        const bf16* ga1 = Al + (size_t)(m0 + lr) * lda + k0 + seg * 8;
        cp_async16(smbase + ((((st*4+0)*128 + lr)*PITCH + seg*8) << 1), ga0, 16);
        cp_async16(smbase + ((((st*4+1)*128 + lr)*PITCH + seg*8) << 1), ga1, 16);
        int rr = n0 + lr;
        int sz = (rr < N) ? 16 : 0;
        int rc = (rr < N) ? rr : 0;
        const bf16* gb0 = Bh + (size_t)rc * ldb + k0 + seg * 8;
        const bf16* gb1 = Bl + (size_t)rc * ldb + k0 + seg * 8;
        cp_async16(smbase + ((((st*4+2)*128 + lr)*PITCH + seg*8) << 1), gb0, sz);
        cp_async16(smbase + ((((st*4+3)*128 + lr)*PITCH + seg*8) << 1), gb1, sz);
    };

    auto compute = [&](int st) {
        uint32_t af[4][2][4], bfr[4][2][2];
        #pragma unroll
        for (int mi = 0; mi < 4; mi++)
            #pragma unroll
            for (int p = 0; p < 2; p++) {
                int row = wm + mi * 16 + (lane & 15);
                uint32_t ad = smbase + ((((st*4+p)*128 + row)*PITCH + (lane >> 4)*8) << 1);
                ldsm4(af[mi][p], ad);
            }
        #pragma unroll
        for (int ni = 0; ni < 4; ni++)
            #pragma unroll
            for (int p = 0; p < 2; p++) {
                int row = wn + ni * 8 + (lane & 7);
                uint32_t ad = smbase + ((((st*4+2+p)*128 + row)*PITCH + ((lane & 8) ? 8 : 0)) << 1);
                ldsm2(bfr[ni][p], ad);
            }
        #pragma unroll
        for (int mi = 0; mi < 4; mi++)
            #pragma unroll
            for (int ni = 0; ni < 4; ni++) {
                mma16816(acc[mi][ni], af[mi][0], bfr[ni][0]);  // hi*hi
                mma16816(acc[mi][ni], af[mi][0], bfr[ni][1]);  // hi*lo
                mma16816(acc[mi][ni], af[mi][1], bfr[ni][0]);  // lo*hi
            }
    };

    issue(0, 0); cp_commit();
    for (int i = 0; i < nk; i++) {
        int cur = i & 1;
        if (i + 1 < nk) { issue(cur ^ 1, (i + 1) << 4); cp_commit(); cp_wait<1>(); }
        else            { cp_wait<0>(); }
        __syncthreads();
        compute(cur);
        __syncthreads();
    }

    const int g = lane >> 2, tg = lane & 3;
    #pragma unroll
    for (int mi = 0; mi < 4; mi++) {
        long long r0 = m0 + wm + mi * 16 + g;
        #pragma unroll
        for (int ni = 0; ni < 4; ni++) {
            int c0 = n0 + wn + ni * 8 + 2 * tg;
            float bv0 = 0.f, bv1 = 0.f;
            if (bias) {
                if (c0 < N)     bv0 = bias[c0];
                if (c0 + 1 < N) bv1 = bias[c0 + 1];
            }
            if (c0 < N) {
                C[r0 * ldc + c0]       = acc[mi][ni][0] + bv0;
                C[(r0 + 8) * ldc + c0] = acc[mi][ni][2] + bv0;
            }
            if (c0 + 1 < N) {
                C[r0 * ldc + c0 + 1]       = acc[mi][ni][1] + bv1;
                C[(r0 + 8) * ldc + c0 + 1] = acc[mi][ni][3] + bv1;
            }
        }
    }
}

// ---------------- fp32 -> (hi,lo) bf16 split, vectorized x4 ----------------
__global__ void __launch_bounds__(256)
split_kernel(const float* __restrict__ in, bf16* __restrict__ hi,
             bf16* __restrict__ lo, long long n4)
{
    long long i = (long long)blockIdx.x * 256 + threadIdx.x;
    if (i >= n4) return;
    float4 v = reinterpret_cast<const float4*>(in)[i];
    float f[4] = {v.x, v.y, v.z, v.w};
    union { bf16 b[4]; uint2 u; } H, L;
    #pragma unroll
    for (int j = 0; j < 4; j++) {
        bf16 h = __float2bfloat16(f[j]);
        H.b[j] = h;
        L.b[j] = __float2bfloat16(f[j] - __bfloat162float(h));
    }
    reinterpret_cast<uint2*>(hi)[i] = H.u;
    reinterpret_cast<uint2*>(lo)[i] = L.u;
}

// ---------------- V transpose + split: KV[m, h*256+128+d] -> Vt[z][d][k] ----
__global__ void __launch_bounds__(256)
vt_split_kernel(const float* __restrict__ KV, bf16* __restrict__ Vth,
                bf16* __restrict__ Vtl)
{
    __shared__ float t[32][33];
    const int z = blockIdx.z, zb = z / NH_, zh = z % NH_;
    const int k0 = blockIdx.x * 32, d0 = blockIdx.y * 32;
    const int tx = threadIdx.x & 31, ty = threadIdx.x >> 5;
    for (int kk = ty; kk < 32; kk += 8)
        t[kk][tx] = KV[((size_t)(zb * S_LEN + k0 + kk)) * NKV
                       + zh * (NOPE_ + VDIM_) + NOPE_ + d0 + tx];
    __syncthreads();
    for (int dd = ty; dd < 32; dd += 8) {
        float v = t[tx][dd];
        bf16 h = __float2bfloat16(v);
        size_t o = ((size_t)z * VDIM_ + d0 + dd) * S_LEN + k0 + tx;
        Vth[o] = h;
        Vtl[o] = __float2bfloat16(v - __bfloat162float(h));
    }
}

// ---------------- RMSNorm ----------------
__global__ void __launch_bounds__(256)
rmsnorm_kernel(const float* __restrict__ in, const float* __restrict__ w,
               float* __restrict__ out, int n, int ldin, int ldout)
{
    long long row = blockIdx.x;
    const float* p = in + row * ldin;
    float s = 0.f;
    for (int i = threadIdx.x; i < n; i += 256) { float v = p[i]; s += v * v; }
    __shared__ float red[256];
    red[threadIdx.x] = s; __syncthreads();
    for (int st = 128; st > 0; st >>= 1) {
        if (threadIdx.x < st) red[threadIdx.x] += red[threadIdx.x + st];
        __syncthreads();
    }
    float scale = rsqrtf(red[0] / (float)n + EPS_);
    for (int i = threadIdx.x; i < n; i += 256)
        out[row * ldout + i] = p[i] * scale * w[i];
}

// ---------------- RoPE Q (in place) ----------------
__global__ void __launch_bounds__(256)
rope_q_kernel(float* __restrict__ Q, const float* __restrict__ freqs)
{
    int idx = blockIdx.x * 256 + threadIdx.x;
    const int total = M_ROWS * NH_ * (ROPE_D / 2);
    if (idx >= total) return;
    int d = idx % (ROPE_D / 2);
    int h = (idx / (ROPE_D / 2)) % NH_;
    int m = idx / ((ROPE_D / 2) * NH_);
    int s = m % S_LEN;
    float f = freqs[s * (ROPE_D / 2) + d];
    float c = cosf(f), sn = sinf(f);
    float* p = Q + (long long)m * NQK + h * QK_ + NOPE_ + 2 * d;
    float x0 = p[0], x1 = p[1];
    p[0] = x0 * c - x1 * sn;
    p[1] = x0 * sn + x1 * c;
}

// ---------------- RoPE K ----------------
__global__ void __launch_bounds__(256)
rope_k_kernel(const float* __restrict__ kvd, float* __restrict__ Krope,
              const float* __restrict__ freqs)
{
    int idx = blockIdx.x * 256 + threadIdx.x;
    const int total = M_ROWS * (ROPE_D / 2);
    if (idx >= total) return;
    int d = idx % (ROPE_D / 2);
    int m = idx / (ROPE_D / 2);
    int s = m % S_LEN;
    float f = freqs[s * (ROPE_D / 2) + d];
    float c = cosf(f), sn = sinf(f);
    const float* p = kvd + (long long)m * KVD_ + KVL + 2 * d;
    float x0 = p[0], x1 = p[1];
    Krope[(long long)m * ROPE_D + 2 * d]     = x0 * c - x1 * sn;
    Krope[(long long)m * ROPE_D + 2 * d + 1] = x0 * sn + x1 * c;
}

// ---------------- K = concat(K_nope, K_rope) ----------------
__global__ void __launch_bounds__(256)
kfull_kernel(const float* __restrict__ KV, const float* __restrict__ Krope,
             float* __restrict__ Kfull)
{
    long long idx = (long long)blockIdx.x * 256 + threadIdx.x;
    const long long total = (long long)M_ROWS * NQK;
    if (idx >= total) return;
    int r = (int)(idx % NQK);
    long long m = idx / NQK;
    int h = r / QK_, d = r % QK_;
    float v = (d < NOPE_) ? KV[m * NKV + h * (NOPE_ + VDIM_) + d]
                          : Krope[m * ROPE_D + (d - NOPE_)];
    Kfull[idx] = v;
}

// ---------------- softmax: fp32 scores -> split bf16 probs ----------------
__global__ void __launch_bounds__(256)
softmax_kernel(const float* __restrict__ scores, const float* __restrict__ mask,
               bf16* __restrict__ ph, bf16* __restrict__ pl, float scale)
{
    long long row = blockIdx.x;                 // z*S + q
    int q = (int)(row % S_LEN);
    const float* p = scores + row * S_LEN;
    const float* mk = mask + (long long)q * S_LEN;
    float vals[8];
    float mx = -3.4e38f;
    #pragma unroll
    for (int j = 0; j < 8; j++) {
        int k = threadIdx.x + j * 256;
        float v = p[k] * scale + mk[k];
        vals[j] = v; mx = fmaxf(mx, v);
    }
    __shared__ float red[256];
    red[threadIdx.x] = mx; __syncthreads();
    for (int st = 128; st > 0; st >>= 1) {
        if (threadIdx.x < st)
            red[threadIdx.x] = fmaxf(red[threadIdx.x], red[threadIdx.x + st]);
        __syncthreads();
    }
    mx = red[0]; __syncthreads();
    float sum = 0.f;
    #pragma unroll
    for (int j = 0; j < 8; j++) { vals[j] = expf(vals[j] - mx); sum += vals[j]; }
    red[threadIdx.x] = sum; __syncthreads();
    for (int st = 128; st > 0; st >>= 1) {
        if (threadIdx.x < st) red[threadIdx.x] += red[threadIdx.x + st];
        __syncthreads();
    }
    float inv = 1.f / red[0];
    #pragma unroll
    for (int j = 0; j < 8; j++) {
        int k = threadIdx.x + j * 256;
        float pv = vals[j] * inv;
        bf16 h = __float2bfloat16(pv);
        ph[row * S_LEN + k] = h;
        pl[row * S_LEN + k] = __float2bfloat16(pv - __bfloat162float(h));
    }
}

// ---------------- host ----------------
extern "C" void kernel_launch(void* const* d_in, const int* in_sizes, int n_in,
                              void* d_out, int out_size)
{
    (void)in_sizes; (void)n_in; (void)out_size;
    const float* x        = (const float*)d_in[0];
    const float* freqs    = (const float*)d_in[1];
    const float* mask     = (const float*)d_in[2];
    const float* Wq_down  = (const float*)d_in[3];
    const float* bq_down  = (const float*)d_in[4];
    const float* q_norm   = (const float*)d_in[5];
    const float* Wq_up    = (const float*)d_in[6];
    const float* bq_up    = (const float*)d_in[7];
    const float* Wkv_down = (const float*)d_in[8];
    const float* bkv_down = (const float*)d_in[9];
    const float* kv_norm  = (const float*)d_in[10];
    const float* Wkv_up   = (const float*)d_in[11];
    const float* bkv_up   = (const float*)d_in[12];
    const float* Wo       = (const float*)d_in[13];
    const float* bo       = (const float*)d_in[14];
    float* out = (float*)d_out;

    void* p;
    #define SYM(var, sym, T) cudaGetSymbolAddress(&p, sym); T* var = (T*)p
    SYM(qmid,  g_qmid,  float);  SYM(qlat,  g_qlat,  float);
    SYM(Qb,    g_Q,     float);  SYM(kvd,   g_kvd,   float);
    SYM(kvlat, g_kvlat, float);  SYM(KVb,   g_KV,    float);
    SYM(Krope, g_Krope, float);  SYM(Kfull, g_Kfull, float);
    SYM(scr,   g_scores,float);  SYM(Ob,    g_O,     float);
    SYM(xh,  g_xh,  bf16); SYM(xl,  g_xl,  bf16);
    SYM(qlh, g_qlh, bf16); SYM(qll, g_qll, bf16);
    SYM(Qh,  g_Qh,  bf16); SYM(Ql,  g_Ql,  bf16);
    SYM(klh, g_klh, bf16); SYM(kll, g_kll, bf16);
    SYM(Kfh, g_Kfh, bf16); SYM(Kfl, g_Kfl, bf16);
    SYM(Vth, g_Vth, bf16); SYM(Vtl, g_Vtl, bf16);
    SYM(ph,  g_ph,  bf16); SYM(pl,  g_pl,  bf16);
    SYM(Oh,  g_Oh,  bf16); SYM(Ol,  g_Ol,  bf16);
    SYM(Wqdh, g_Wqdh, bf16); SYM(Wqdl, g_Wqdl, bf16);
    SYM(Wquh, g_Wquh, bf16); SYM(Wqul, g_Wqul, bf16);
    SYM(Wkdh, g_Wkdh, bf16); SYM(Wkdl, g_Wkdl, bf16);
    SYM(Wkuh, g_Wkuh, bf16); SYM(Wkul, g_Wkul, bf16);
    SYM(Woh,  g_Woh,  bf16); SYM(Wol,  g_Wol,  bf16);
    #undef SYM

    const float scale = 1.0f / sqrtf((float)QK_);
    const long long Z0 = 0;
    #define SPLIT(src, h, l, n) split_kernel<<<(int)(((n)/4 + 255)/256), 256>>>(src, h, l, (n)/4)

    // split input + weights
    SPLIT(x,        xh,   xl,   (long long)M_ROWS*DIM_);
    SPLIT(Wq_down,  Wqdh, Wqdl, (long long)QL*DIM_);
    SPLIT(Wq_up,    Wquh, Wqul, (long long)NQK*QL);
    SPLIT(Wkv_down, Wkdh, Wkdl, (long long)KVD_*DIM_);
    SPLIT(Wkv_up,   Wkuh, Wkul, (long long)NKV*KVL);
    SPLIT(Wo,       Woh,  Wol,  (long long)DIM_*DIM_);

    // 1) q_mid = x @ Wq_down^T + b
    mma_gemm<false,false><<<dim3(QL/128, M_ROWS/128, 1), 256>>>(
        xh, xl, Wqdh, Wqdl, bq_down, qmid, M_ROWS, QL, DIM_, DIM_, DIM_, QL,
        Z0,Z0,Z0,Z0,Z0,Z0);
    // 2) rmsnorm + split
    rmsnorm_kernel<<<M_ROWS, 256>>>(qmid, q_norm, qlat, QL, QL, QL);
    SPLIT(qlat, qlh, qll, (long long)M_ROWS*QL);
    // 3) Q = q_lat @ Wq_up^T + b, rope, split
    mma_gemm<false,false><<<dim3(NQK/128, M_ROWS/128, 1), 256>>>(
        qlh, qll, Wquh, Wqul, bq_up, Qb, M_ROWS, NQK, QL, QL, QL, NQK,
        Z0,Z0,Z0,Z0,Z0,Z0);
    rope_q_kernel<<<(M_ROWS*NH_*(ROPE_D/2) + 255)/256, 256>>>(Qb, freqs);
    SPLIT(Qb, Qh, Ql, (long long)M_ROWS*NQK);
    // 4) kvd = x @ Wkv_down^T + b  (N=576, guarded)
    mma_gemm<false,false><<<dim3((KVD_+127)/128, M_ROWS/128, 1), 256>>>(
        xh, xl, Wkdh, Wkdl, bkv_down, kvd, M_ROWS, KVD_, DIM_, DIM_, DIM_, KVD_,
        Z0,Z0,Z0,Z0,Z0,Z0);
    // 5) rmsnorm + split; rope K
    rmsnorm_kernel<<<M_ROWS, 256>>>(kvd, kv_norm, kvlat, KVL, KVD_, KVL);
    SPLIT(kvlat, klh, kll, (long long)M_ROWS*KVL);
    rope_k_kernel<<<(M_ROWS*(ROPE_D/2) + 255)/256, 256>>>(kvd, Krope, freqs);
    // 6) KV = kv_lat @ Wkv_up^T + b
    mma_gemm<false,false><<<dim3(NKV/128, M_ROWS/128, 1), 256>>>(
        klh, kll, Wkuh, Wkul, bkv_up, KVb, M_ROWS, NKV, KVL, KVL, KVL, NKV,
        Z0,Z0,Z0,Z0,Z0,Z0);
    // 7) assemble + split K; transpose + split V
    kfull_kernel<<<(int)(((long long)M_ROWS*NQK + 255)/256), 256>>>(KVb, Krope, Kfull);
    SPLIT(Kfull, Kfh, Kfl, (long long)M_ROWS*NQK);
    vt_split_kernel<<<dim3(S_LEN/32, VDIM_/32, BATCH*NH_), 256>>>(KVb, Vth, Vtl);
    // 8) scores = Q @ K^T (causal skip)
    mma_gemm<true,false><<<dim3(S_LEN/128, S_LEN/128, BATCH*NH_), 256>>>(
        Qh, Ql, Kfh, Kfl, nullptr, scr, S_LEN, S_LEN, QK_, NQK, NQK, S_LEN,
        (long long)S_LEN*NQK, (long long)QK_,
        (long long)S_LEN*NQK, (long long)QK_,
        (long long)NH_*S_LEN*S_LEN, (long long)S_LEN*S_LEN);
    // 9) softmax -> split probs
    softmax_kernel<<<BATCH*NH_*S_LEN, 256>>>(scr, mask, ph, pl, scale);
    // 10) O = P @ V (K truncated at diagonal)
    mma_gemm<false,true><<<dim3(1, S_LEN/128, BATCH*NH_), 256>>>(
        ph, pl, Vth, Vtl, nullptr, Ob, S_LEN, VDIM_, S_LEN, S_LEN, S_LEN, NH_*VDIM_,
        (long long)NH_*S_LEN*S_LEN, (long long)S_LEN*S_LEN,
        (long long)NH_*VDIM_*S_LEN, (long long)VDIM_*S_LEN,
        (long long)S_LEN*(NH_*VDIM_), (long long)VDIM_);
    // 11) split O; out = O @ Wo^T + b
    SPLIT(Ob, Oh, Ol, (long long)M_ROWS*DIM_);
    mma_gemm<false,false><<<dim3(DIM_/128, M_ROWS/128, 1), 256>>>(
        Oh, Ol, Woh, Wol, bo, out, M_ROWS, DIM_, NH_*VDIM_, NH_*VDIM_, NH_*VDIM_, DIM_,
        Z0,Z0,Z0,Z0,Z0,Z0);
    #undef SPLIT
}

// round 4
// speedup vs baseline: 2.4793x; 1.1597x over previous
#include <cuda_runtime.h>
#include <cuda_bf16.h>
#include <math.h>
#include <stdint.h>

typedef __nv_bfloat16 bf16;

// ---------------- problem constants ----------------
#define S_LEN   2048
#define BATCH   2
#define M_ROWS  4096
#define DIM_    2048
#define QL      1536
#define NH_     16
#define QK_     192
#define NOPE_   128
#define ROPE_D  64
#define VDIM_   128
#define KVL     512
#define KVD_    576
#define NQK     (NH_*QK_)            // 3072
#define NKV     (NH_*(NOPE_+VDIM_))  // 4096
#define EPS_    1.1920929e-07f
#define PITCH   24                   // gemm smem pitch (bf16)
#define QP      200                  // flash Q/K smem pitch (bf16)
#define VP      136                  // flash V smem pitch (bf16)

// ---------------- scratch ----------------
__device__ float g_qmid [(size_t)M_ROWS * QL];
__device__ float g_Q    [(size_t)M_ROWS * NQK];
__device__ float g_kvd  [(size_t)M_ROWS * KVD_];
__device__ float g_KV   [(size_t)M_ROWS * NKV];

__device__ bf16 g_xh [(size_t)M_ROWS*DIM_],  g_xl [(size_t)M_ROWS*DIM_];
__device__ bf16 g_qlh[(size_t)M_ROWS*QL],    g_qll[(size_t)M_ROWS*QL];
__device__ bf16 g_klh[(size_t)M_ROWS*KVL],   g_kll[(size_t)M_ROWS*KVL];
// flash-layout tensors [z][s][*]
__device__ bf16 g_Qzh[(size_t)BATCH*NH_*S_LEN*QK_],  g_Qzl[(size_t)BATCH*NH_*S_LEN*QK_];
__device__ bf16 g_Kfh[(size_t)BATCH*NH_*S_LEN*QK_],  g_Kfl[(size_t)BATCH*NH_*S_LEN*QK_];
__device__ bf16 g_Vzh[(size_t)BATCH*NH_*S_LEN*VDIM_],g_Vzl[(size_t)BATCH*NH_*S_LEN*VDIM_];
__device__ bf16 g_Oh [(size_t)M_ROWS*DIM_], g_Ol [(size_t)M_ROWS*DIM_];
// weight splits
__device__ bf16 g_Wqdh[(size_t)QL*DIM_],   g_Wqdl[(size_t)QL*DIM_];
__device__ bf16 g_Wquh[(size_t)NQK*QL],    g_Wqul[(size_t)NQK*QL];
__device__ bf16 g_Wkdh[(size_t)KVD_*DIM_], g_Wkdl[(size_t)KVD_*DIM_];
__device__ bf16 g_Wkuh[(size_t)NKV*KVL],   g_Wkul[(size_t)NKV*KVL];
__device__ bf16 g_Woh [(size_t)DIM_*DIM_], g_Wol [(size_t)DIM_*DIM_];

// ---------------- PTX helpers ----------------
__device__ __forceinline__ void cp_async16(uint32_t saddr, const void* g, int sz) {
    asm volatile("cp.async.ca.shared.global [%0], [%1], 16, %2;\n"
                 :: "r"(saddr), "l"(g), "r"(sz));
}
__device__ __forceinline__ void cp_commit() { asm volatile("cp.async.commit_group;\n"); }
template<int N> __device__ __forceinline__ void cp_wait() {
    asm volatile("cp.async.wait_group %0;\n" :: "n"(N));
}
__device__ __forceinline__ void ldsm4(uint32_t a[4], uint32_t addr) {
    asm volatile("ldmatrix.sync.aligned.m8n8.x4.shared.b16 {%0,%1,%2,%3}, [%4];\n"
                 : "=r"(a[0]), "=r"(a[1]), "=r"(a[2]), "=r"(a[3]) : "r"(addr));
}
__device__ __forceinline__ void ldsm4t(uint32_t a[4], uint32_t addr) {
    asm volatile("ldmatrix.sync.aligned.m8n8.x4.trans.shared.b16 {%0,%1,%2,%3}, [%4];\n"
                 : "=r"(a[0]), "=r"(a[1]), "=r"(a[2]), "=r"(a[3]) : "r"(addr));
}
__device__ __forceinline__ void ldsm2(uint32_t b[2], uint32_t addr) {
    asm volatile("ldmatrix.sync.aligned.m8n8.x2.shared.b16 {%0,%1}, [%2];\n"
                 : "=r"(b[0]), "=r"(b[1]) : "r"(addr));
}
__device__ __forceinline__ void mma16816(float c[4], const uint32_t a[4], const uint32_t b[2]) {
    asm volatile(
        "mma.sync.aligned.m16n8k16.row.col.f32.bf16.bf16.f32 "
        "{%0,%1,%2,%3}, {%4,%5,%6,%7}, {%8,%9}, {%0,%1,%2,%3};\n"
        : "+f"(c[0]), "+f"(c[1]), "+f"(c[2]), "+f"(c[3])
        : "r"(a[0]), "r"(a[1]), "r"(a[2]), "r"(a[3]), "r"(b[0]), "r"(b[1]));
}
__device__ __forceinline__ void split1(float v, bf16& h, bf16& l) {
    h = __float2bfloat16(v);
    l = __float2bfloat16(v - __bfloat162float(h));
}
__device__ __forceinline__ void split2(float a, float b, uint32_t& h, uint32_t& l) {
    __nv_bfloat162 hh = __floats2bfloat162_rn(a, b);
    float ra = a - __bfloat162float(hh.x);
    float rb = b - __bfloat162float(hh.y);
    __nv_bfloat162 ll = __floats2bfloat162_rn(ra, rb);
    h = *reinterpret_cast<uint32_t*>(&hh);
    l = *reinterpret_cast<uint32_t*>(&ll);
}

// ---------------- split-bf16 tensor-core GEMM (proven round-3 mainloop) ----
// C[M,N] = (Ah+Al)[M,K] * (Bh+Bl)[N,K]^T + bias
__global__ void __launch_bounds__(256)
mma_gemm(const bf16* __restrict__ Ah, const bf16* __restrict__ Al,
         const bf16* __restrict__ Bh, const bf16* __restrict__ Bl,
         const float* __restrict__ bias, float* __restrict__ C,
         int M, int N, int K, int lda, int ldb, int ldc)
{
    __shared__ bf16 sm[2][4][128][PITCH];

    const int m0 = blockIdx.y * 128, n0 = blockIdx.x * 128;
    const int nk = K >> 4;
    const int tid = threadIdx.x, lane = tid & 31, warp = tid >> 5;
    const int wm = (warp >> 2) * 64, wn = (warp & 3) * 32;
    const int lr = tid >> 1, seg = tid & 1;
    const uint32_t smbase = (uint32_t)__cvta_generic_to_shared(&sm[0][0][0][0]);

    float acc[4][4][4];
    #pragma unroll
    for (int i = 0; i < 4; i++)
        #pragma unroll
        for (int j = 0; j < 4; j++)
            #pragma unroll
            for (int r = 0; r < 4; r++) acc[i][j][r] = 0.f;

    auto issue = [&](int st, int k0) {
        const bf16* ga0 = Ah + (size_t)(m0 + lr) * lda + k0 + seg * 8;
        const bf16* ga1 = Al + (size_t)(m0 + lr) * lda + k0 + seg * 8;
        cp_async16(smbase + ((((st*4+0)*128 + lr)*PITCH + seg*8) << 1), ga0, 16);
        cp_async16(smbase + ((((st*4+1)*128 + lr)*PITCH + seg*8) << 1), ga1, 16);
        int rr = n0 + lr;
        int sz = (rr < N) ? 16 : 0;
        int rc = (rr < N) ? rr : 0;
        const bf16* gb0 = Bh + (size_t)rc * ldb + k0 + seg * 8;
        const bf16* gb1 = Bl + (size_t)rc * ldb + k0 + seg * 8;
        cp_async16(smbase + ((((st*4+2)*128 + lr)*PITCH + seg*8) << 1), gb0, sz);
        cp_async16(smbase + ((((st*4+3)*128 + lr)*PITCH + seg*8) << 1), gb1, sz);
    };

    auto compute = [&](int st) {
        uint32_t af[4][2][4], bfr[4][2][2];
        #pragma unroll
        for (int mi = 0; mi < 4; mi++)
            #pragma unroll
            for (int p = 0; p < 2; p++) {
                int row = wm + mi * 16 + (lane & 15);
                uint32_t ad = smbase + ((((st*4+p)*128 + row)*PITCH + (lane >> 4)*8) << 1);
                ldsm4(af[mi][p], ad);
            }
        #pragma unroll
        for (int ni = 0; ni < 4; ni++)
            #pragma unroll
            for (int p = 0; p < 2; p++) {
                int row = wn + ni * 8 + (lane & 7);
                uint32_t ad = smbase + ((((st*4+2+p)*128 + row)*PITCH + ((lane & 8) ? 8 : 0)) << 1);
                ldsm2(bfr[ni][p], ad);
            }
        #pragma unroll
        for (int mi = 0; mi < 4; mi++)
            #pragma unroll
            for (int ni = 0; ni < 4; ni++) {
                mma16816(acc[mi][ni], af[mi][0], bfr[ni][0]);
                mma16816(acc[mi][ni], af[mi][0], bfr[ni][1]);
                mma16816(acc[mi][ni], af[mi][1], bfr[ni][0]);
            }
    };

    issue(0, 0); cp_commit();
    for (int i = 0; i < nk; i++) {
        int cur = i & 1;
        if (i + 1 < nk) { issue(cur ^ 1, (i + 1) << 4); cp_commit(); cp_wait<1>(); }
        else            { cp_wait<0>(); }
        __syncthreads();
        compute(cur);
        __syncthreads();
    }

    const int g = lane >> 2, tg = lane & 3;
    #pragma unroll
    for (int mi = 0; mi < 4; mi++) {
        long long r0 = m0 + wm + mi * 16 + g;
        #pragma unroll
        for (int ni = 0; ni < 4; ni++) {
            int c0 = n0 + wn + ni * 8 + 2 * tg;
            float bv0 = 0.f, bv1 = 0.f;
            if (bias) {
                if (c0 < N)     bv0 = bias[c0];
                if (c0 + 1 < N) bv1 = bias[c0 + 1];
            }
            if (c0 < N) {
                C[r0 * ldc + c0]       = acc[mi][ni][0] + bv0;
                C[(r0 + 8) * ldc + c0] = acc[mi][ni][2] + bv0;
            }
            if (c0 + 1 < N) {
                C[r0 * ldc + c0 + 1]       = acc[mi][ni][1] + bv1;
                C[(r0 + 8) * ldc + c0 + 1] = acc[mi][ni][3] + bv1;
            }
        }
    }
}

// ---------------- fused flash attention ----------------
// grid(16, 32): blockIdx.y = z = zb*16+zh ; mt = 15 - blockIdx.x (long tiles first)
// Q tile 128x192 (hi/lo) persistent; K tiles 64x192; V tiles 64x128 (k-major).
__global__ void __launch_bounds__(256, 1)
flash_kernel(const bf16* __restrict__ Qh, const bf16* __restrict__ Ql,
             const bf16* __restrict__ Kh, const bf16* __restrict__ Kl,
             const bf16* __restrict__ Vh, const bf16* __restrict__ Vl,
             bf16* __restrict__ Oh, bf16* __restrict__ Ol)
{
    extern __shared__ bf16 fs[];
    bf16* Qhs = fs;
    bf16* Qls = Qhs + 128 * QP;
    bf16* Khs = Qls + 128 * QP;
    bf16* Kls = Khs + 64 * QP;
    bf16* Vhs = Kls + 64 * QP;
    bf16* Vls = Vhs + 64 * VP;

    const int z = blockIdx.y, zb = z >> 4, zh = z & 15;
    const int mt = (int)gridDim.x - 1 - (int)blockIdx.x;
    const int m0 = mt * 128;
    const int tid = threadIdx.x, lane = tid & 31, warp = tid >> 5;
    const int g = lane >> 2, tg = lane & 3;
    const int wr = warp * 16;

    const uint32_t sQh = (uint32_t)__cvta_generic_to_shared(Qhs);
    const uint32_t sQl = (uint32_t)__cvta_generic_to_shared(Qls);
    const uint32_t sKh = (uint32_t)__cvta_generic_to_shared(Khs);
    const uint32_t sKl = (uint32_t)__cvta_generic_to_shared(Kls);
    const uint32_t sVh = (uint32_t)__cvta_generic_to_shared(Vhs);
    const uint32_t sVl = (uint32_t)__cvta_generic_to_shared(Vls);

    const size_t qzb = (size_t)z * S_LEN * QK_;
    const size_t vzb = (size_t)z * S_LEN * VDIM_;

    // load Q tile once
    for (int i = tid; i < 128 * 24; i += 256) {
        int r = i / 24, c = (i % 24) * 8;
        size_t go = qzb + (size_t)(m0 + r) * QK_ + c;
        uint32_t so = (uint32_t)((r * QP + c) * 2);
        cp_async16(sQh + so, Qh + go, 16);
        cp_async16(sQl + so, Ql + go, 16);
    }
    cp_commit();

    float mr0 = -1e30f, mr1 = -1e30f, lr0 = 0.f, lr1 = 0.f;
    float oacc[16][4];
    #pragma unroll
    for (int i = 0; i < 16; i++)
        #pragma unroll
        for (int j = 0; j < 4; j++) oacc[i][j] = 0.f;

    const int nkt = (m0 + 128) / 64;
    for (int kt = 0; kt < nkt; kt++) {
        const int k0 = kt * 64;
        // load K,V tile
        for (int i = tid; i < 64 * 24; i += 256) {
            int r = i / 24, c = (i % 24) * 8;
            size_t go = qzb + (size_t)(k0 + r) * QK_ + c;
            uint32_t so = (uint32_t)((r * QP + c) * 2);
            cp_async16(sKh + so, Kh + go, 16);
            cp_async16(sKl + so, Kl + go, 16);
        }
        for (int i = tid; i < 64 * 16; i += 256) {
            int r = i / 16, c = (i % 16) * 8;
            size_t go = vzb + (size_t)(k0 + r) * VDIM_ + c;
            uint32_t so = (uint32_t)((r * VP + c) * 2);
            cp_async16(sVh + so, Vh + go, 16);
            cp_async16(sVl + so, Vl + go, 16);
        }
        cp_commit();
        cp_wait<0>();
        __syncthreads();

        // ---- S = Q @ K^T  (128x64 per CTA; 16 rows per warp) ----
        float sacc[8][4];
        #pragma unroll
        for (int i = 0; i < 8; i++)
            #pragma unroll
            for (int j = 0; j < 4; j++) sacc[i][j] = 0.f;

        #pragma unroll
        for (int ks = 0; ks < 12; ks++) {
            uint32_t ah[4], al[4];
            uint32_t aoff = (uint32_t)(((wr + (lane & 15)) * QP + ks * 16 + (lane >> 4) * 8) * 2);
            ldsm4(ah, sQh + aoff);
            ldsm4(al, sQl + aoff);
            #pragma unroll
            for (int np = 0; np < 4; np++) {
                uint32_t kh4[4], kl4[4];
                uint32_t boff = (uint32_t)(((np * 16 + (lane & 15)) * QP + ks * 16 + (lane >> 4) * 8) * 2);
                ldsm4(kh4, sKh + boff);
                ldsm4(kl4, sKl + boff);
                uint32_t b0h[2] = {kh4[0], kh4[2]}, b1h[2] = {kh4[1], kh4[3]};
                uint32_t b0l[2] = {kl4[0], kl4[2]}, b1l[2] = {kl4[1], kl4[3]};
                mma16816(sacc[2*np],   ah, b0h);
                mma16816(sacc[2*np],   ah, b0l);
                mma16816(sacc[2*np],   al, b0h);
                mma16816(sacc[2*np+1], ah, b1h);
                mma16816(sacc[2*np+1], ah, b1l);
                mma16816(sacc[2*np+1], al, b1h);
            }
        }

        // ---- causal mask (only near-diagonal tiles) ----
        if (k0 + 63 > m0) {
            int r0 = m0 + wr + g, r1 = r0 + 8;
            #pragma unroll
            for (int ni = 0; ni < 8; ni++) {
                int c0 = k0 + ni * 8 + 2 * tg;
                if (c0     > r0) sacc[ni][0] = -1e30f;
                if (c0 + 1 > r0) sacc[ni][1] = -1e30f;
                if (c0     > r1) sacc[ni][2] = -1e30f;
                if (c0 + 1 > r1) sacc[ni][3] = -1e30f;
            }
        }

        // ---- online softmax (rows g / g+8; stats across 4 tg lanes) ----
        float mx0 = -1e30f, mx1 = -1e30f;
        #pragma unroll
        for (int ni = 0; ni < 8; ni++) {
            mx0 = fmaxf(mx0, fmaxf(sacc[ni][0], sacc[ni][1]));
            mx1 = fmaxf(mx1, fmaxf(sacc[ni][2], sacc[ni][3]));
        }
        mx0 = fmaxf(mx0, __shfl_xor_sync(0xffffffffu, mx0, 1));
        mx0 = fmaxf(mx0, __shfl_xor_sync(0xffffffffu, mx0, 2));
        mx1 = fmaxf(mx1, __shfl_xor_sync(0xffffffffu, mx1, 1));
        mx1 = fmaxf(mx1, __shfl_xor_sync(0xffffffffu, mx1, 2));
        float nm0 = fmaxf(mr0, mx0), nm1 = fmaxf(mr1, mx1);
        float al0 = __expf(mr0 - nm0), al1 = __expf(mr1 - nm1);
        mr0 = nm0; mr1 = nm1;
        float s0 = 0.f, s1 = 0.f;
        #pragma unroll
        for (int ni = 0; ni < 8; ni++) {
            sacc[ni][0] = __expf(sacc[ni][0] - nm0);
            sacc[ni][1] = __expf(sacc[ni][1] - nm0);
            sacc[ni][2] = __expf(sacc[ni][2] - nm1);
            sacc[ni][3] = __expf(sacc[ni][3] - nm1);
            s0 += sacc[ni][0] + sacc[ni][1];
            s1 += sacc[ni][2] + sacc[ni][3];
        }
        s0 += __shfl_xor_sync(0xffffffffu, s0, 1);
        s0 += __shfl_xor_sync(0xffffffffu, s0, 2);
        s1 += __shfl_xor_sync(0xffffffffu, s1, 1);
        s1 += __shfl_xor_sync(0xffffffffu, s1, 2);
        lr0 = lr0 * al0 + s0;
        lr1 = lr1 * al1 + s1;
        #pragma unroll
        for (int i = 0; i < 16; i++) {
            oacc[i][0] *= al0; oacc[i][1] *= al0;
            oacc[i][2] *= al1; oacc[i][3] *= al1;
        }

        // ---- O += P @ V  (P split to bf16 straight from registers) ----
        #pragma unroll
        for (int kk = 0; kk < 4; kk++) {
            uint32_t pah[4], pal[4];
            split2(sacc[2*kk][0],   sacc[2*kk][1],   pah[0], pal[0]);
            split2(sacc[2*kk][2],   sacc[2*kk][3],   pah[1], pal[1]);
            split2(sacc[2*kk+1][0], sacc[2*kk+1][1], pah[2], pal[2]);
            split2(sacc[2*kk+1][2], sacc[2*kk+1][3], pah[3], pal[3]);
            #pragma unroll
            for (int np = 0; np < 8; np++) {
                uint32_t vh4[4], vl4[4];
                uint32_t voff = (uint32_t)(((kk * 16 + (lane & 15)) * VP + np * 16 + (lane >> 4) * 8) * 2);
                ldsm4t(vh4, sVh + voff);
                ldsm4t(vl4, sVl + voff);
                uint32_t bh0[2] = {vh4[0], vh4[1]}, bh1[2] = {vh4[2], vh4[3]};
                uint32_t bl0[2] = {vl4[0], vl4[1]}, bl1[2] = {vl4[2], vl4[3]};
                mma16816(oacc[2*np],   pah, bh0);
                mma16816(oacc[2*np],   pah, bl0);
                mma16816(oacc[2*np],   pal, bh0);
                mma16816(oacc[2*np+1], pah, bh1);
                mma16816(oacc[2*np+1], pah, bl1);
                mma16816(oacc[2*np+1], pal, bh1);
            }
        }
        __syncthreads();
    }

    // ---- epilogue: O/l, split, store ----
    float i0 = 1.f / lr0, i1 = 1.f / lr1;
    size_t row0 = (size_t)(zb * S_LEN + m0 + wr + g) * DIM_ + zh * VDIM_;
    size_t row1 = row0 + (size_t)8 * DIM_;
    #pragma unroll
    for (int ni = 0; ni < 16; ni++) {
        int d = ni * 8 + 2 * tg;
        uint32_t h0, l0, h1, l1;
        split2(oacc[ni][0] * i0, oacc[ni][1] * i0, h0, l0);
        split2(oacc[ni][2] * i1, oacc[ni][3] * i1, h1, l1);
        *reinterpret_cast<uint32_t*>(Oh + row0 + d) = h0;
        *reinterpret_cast<uint32_t*>(Ol + row0 + d) = l0;
        *reinterpret_cast<uint32_t*>(Oh + row1 + d) = h1;
        *reinterpret_cast<uint32_t*>(Ol + row1 + d) = l1;
    }
}

// ---------------- fp32 -> (hi,lo) split, vectorized x4 ----------------
__global__ void __launch_bounds__(256)
split_kernel(const float* __restrict__ in, bf16* __restrict__ hi,
             bf16* __restrict__ lo, long long n4)
{
    long long i = (long long)blockIdx.x * 256 + threadIdx.x;
    if (i >= n4) return;
    float4 v = reinterpret_cast<const float4*>(in)[i];
    float f[4] = {v.x, v.y, v.z, v.w};
    union { bf16 b[4]; uint2 u; } H, L;
    #pragma unroll
    for (int j = 0; j < 4; j++) split1(f[j], H.b[j], L.b[j]);
    reinterpret_cast<uint2*>(hi)[i] = H.u;
    reinterpret_cast<uint2*>(lo)[i] = L.u;
}

// ---------------- RMSNorm + split ----------------
__global__ void __launch_bounds__(256)
rmsnorm_split_kernel(const float* __restrict__ in, const float* __restrict__ w,
                     bf16* __restrict__ outh, bf16* __restrict__ outl,
                     int n, int ldin)
{
    long long row = blockIdx.x;
    const float* p = in + row * ldin;
    float s = 0.f;
    for (int i = threadIdx.x; i < n; i += 256) { float v = p[i]; s += v * v; }
    __shared__ float red[256];
    red[threadIdx.x] = s; __syncthreads();
    for (int st = 128; st > 0; st >>= 1) {
        if (threadIdx.x < st) red[threadIdx.x] += red[threadIdx.x + st];
        __syncthreads();
    }
    float scale = rsqrtf(red[0] / (float)n + EPS_);
    for (int i = threadIdx.x; i < n; i += 256) {
        float v = p[i] * scale * w[i];
        split1(v, outh[row * n + i], outl[row * n + i]);
    }
}

// ---------------- Q post: rope + scale + split -> [z][s][192] ----------------
__global__ void __launch_bounds__(256)
q_post_kernel(const float* __restrict__ Qb, const float* __restrict__ freqs,
              bf16* __restrict__ Qzh, bf16* __restrict__ Qzl, float scale)
{
    int idx = blockIdx.x * 256 + threadIdx.x;
    const int total = M_ROWS * NH_ * (QK_ / 2);
    if (idx >= total) return;
    int dp = idx % (QK_ / 2);
    int h  = (idx / (QK_ / 2)) % NH_;
    int m  = idx / ((QK_ / 2) * NH_);
    int s  = m & (S_LEN - 1);
    int zb = m >> 11;
    float x0 = Qb[(size_t)m * NQK + h * QK_ + 2 * dp];
    float x1 = Qb[(size_t)m * NQK + h * QK_ + 2 * dp + 1];
    float y0 = x0, y1 = x1;
    if (dp >= NOPE_ / 2) {
        float f = freqs[s * (ROPE_D / 2) + (dp - NOPE_ / 2)];
        float c = cosf(f), sn = sinf(f);
        y0 = x0 * c - x1 * sn;
        y1 = x0 * sn + x1 * c;
    }
    y0 *= scale; y1 *= scale;
    size_t o = ((size_t)(zb * NH_ + h) * S_LEN + s) * QK_ + 2 * dp;
    split1(y0, Qzh[o],     Qzl[o]);
    split1(y1, Qzh[o + 1], Qzl[o + 1]);
}

// ---------------- KV post: unpack K_nope + V, split -> [z][s][*] -------------
__global__ void __launch_bounds__(256)
kv_post_kernel(const float* __restrict__ KV,
               bf16* __restrict__ Kfh, bf16* __restrict__ Kfl,
               bf16* __restrict__ Vzh, bf16* __restrict__ Vzl)
{
    long long idx = (long long)blockIdx.x * 256 + threadIdx.x;
    const long long total = (long long)M_ROWS * NH_ * (NOPE_ + VDIM_);
    if (idx >= total) return;
    int d = (int)(idx % (NOPE_ + VDIM_));
    int h = (int)((idx / (NOPE_ + VDIM_)) % NH_);
    long long m = idx / ((NOPE_ + VDIM_) * NH_);
    int s  = (int)(m & (S_LEN - 1));
    int zb = (int)(m >> 11);
    int z  = zb * NH_ + h;
    float v = KV[m * NKV + h * (NOPE_ + VDIM_) + d];
    if (d < NOPE_) {
        size_t o = ((size_t)z * S_LEN + s) * QK_ + d;
        split1(v, Kfh[o], Kfl[o]);
    } else {
        size_t o = ((size_t)z * S_LEN + s) * VDIM_ + (d - NOPE_);
        split1(v, Vzh[o], Vzl[o]);
    }
}

// ---------------- K rope part: rope(kvd cols 512..575) -> Kf cols 128..191 ---
__global__ void __launch_bounds__(256)
k_rope_kernel(const float* __restrict__ kvd, const float* __restrict__ freqs,
              bf16* __restrict__ Kfh, bf16* __restrict__ Kfl)
{
    int idx = blockIdx.x * 256 + threadIdx.x;
    const int total = M_ROWS * (ROPE_D / 2);
    if (idx >= total) return;
    int dp = idx % (ROPE_D / 2);
    int m  = idx / (ROPE_D / 2);
    int s  = m & (S_LEN - 1);
    int zb = m >> 11;
    float f = freqs[s * (ROPE_D / 2) + dp];
    float c = cosf(f), sn = sinf(f);
    float x0 = kvd[(size_t)m * KVD_ + KVL + 2 * dp];
    float x1 = kvd[(size_t)m * KVD_ + KVL + 2 * dp + 1];
    float y0 = x0 * c - x1 * sn;
    float y1 = x0 * sn + x1 * c;
    bf16 h0, l0, h1, l1;
    split1(y0, h0, l0);
    split1(y1, h1, l1);
    #pragma unroll
    for (int h = 0; h < NH_; h++) {
        size_t o = ((size_t)(zb * NH_ + h) * S_LEN + s) * QK_ + NOPE_ + 2 * dp;
        Kfh[o] = h0; Kfl[o] = l0;
        Kfh[o + 1] = h1; Kfl[o + 1] = l1;
    }
}

// ---------------- host ----------------
extern "C" void kernel_launch(void* const* d_in, const int* in_sizes, int n_in,
                              void* d_out, int out_size)
{
    (void)in_sizes; (void)n_in; (void)out_size;
    const float* x        = (const float*)d_in[0];
    const float* freqs    = (const float*)d_in[1];
    // d_in[2] = causal_mask (unused: causality handled analytically)
    const float* Wq_down  = (const float*)d_in[3];
    const float* bq_down  = (const float*)d_in[4];
    const float* q_norm   = (const float*)d_in[5];
    const float* Wq_up    = (const float*)d_in[6];
    const float* bq_up    = (const float*)d_in[7];
    const float* Wkv_down = (const float*)d_in[8];
    const float* bkv_down = (const float*)d_in[9];
    const float* kv_norm  = (const float*)d_in[10];
    const float* Wkv_up   = (const float*)d_in[11];
    const float* bkv_up   = (const float*)d_in[12];
    const float* Wo       = (const float*)d_in[13];
    const float* bo       = (const float*)d_in[14];
    float* out = (float*)d_out;

    void* p;
    #define SYM(var, sym, T) cudaGetSymbolAddress(&p, sym); T* var = (T*)p
    SYM(qmid,  g_qmid,  float);  SYM(Qb,    g_Q,     float);
    SYM(kvd,   g_kvd,   float);  SYM(KVb,   g_KV,    float);
    SYM(xh,  g_xh,  bf16); SYM(xl,  g_xl,  bf16);
    SYM(qlh, g_qlh, bf16); SYM(qll, g_qll, bf16);
    SYM(klh, g_klh, bf16); SYM(kll, g_kll, bf16);
    SYM(Qzh, g_Qzh, bf16); SYM(Qzl, g_Qzl, bf16);
    SYM(Kfh, g_Kfh, bf16); SYM(Kfl, g_Kfl, bf16);
    SYM(Vzh, g_Vzh, bf16); SYM(Vzl, g_Vzl, bf16);
    SYM(Oh,  g_Oh,  bf16); SYM(Ol,  g_Ol,  bf16);
    SYM(Wqdh, g_Wqdh, bf16); SYM(Wqdl, g_Wqdl, bf16);
    SYM(Wquh, g_Wquh, bf16); SYM(Wqul, g_Wqul, bf16);
    SYM(Wkdh, g_Wkdh, bf16); SYM(Wkdl, g_Wkdl, bf16);
    SYM(Wkuh, g_Wkuh, bf16); SYM(Wkul, g_Wkul, bf16);
    SYM(Woh,  g_Woh,  bf16); SYM(Wol,  g_Wol,  bf16);
    #undef SYM

    const float scale = 1.0f / sqrtf((float)QK_);
    const int FLASH_SMEM = (2 * 128 * QP + 2 * 64 * QP + 2 * 64 * VP) * 2;
    cudaFuncSetAttribute(flash_kernel, cudaFuncAttributeMaxDynamicSharedMemorySize,
                         FLASH_SMEM);

    #define SPLIT(src, h, l, n) split_kernel<<<(int)(((n)/4 + 255)/256), 256>>>(src, h, l, (n)/4)
    SPLIT(x,        xh,   xl,   (long long)M_ROWS*DIM_);
    SPLIT(Wq_down,  Wqdh, Wqdl, (long long)QL*DIM_);
    SPLIT(Wq_up,    Wquh, Wqul, (long long)NQK*QL);
    SPLIT(Wkv_down, Wkdh, Wkdl, (long long)KVD_*DIM_);
    SPLIT(Wkv_up,   Wkuh, Wkul, (long long)NKV*KVL);
    SPLIT(Wo,       Woh,  Wol,  (long long)DIM_*DIM_);
    #undef SPLIT

    // 1) q_mid = x @ Wq_down^T + b
    mma_gemm<<<dim3(QL/128, M_ROWS/128), 256>>>(
        xh, xl, Wqdh, Wqdl, bq_down, qmid, M_ROWS, QL, DIM_, DIM_, DIM_, QL);
    // 2) q_lat = rmsnorm(q_mid) -> split
    rmsnorm_split_kernel<<<M_ROWS, 256>>>(qmid, q_norm, qlh, qll, QL, QL);
    // 3) Q = q_lat @ Wq_up^T + b
    mma_gemm<<<dim3(NQK/128, M_ROWS/128), 256>>>(
        qlh, qll, Wquh, Wqul, bq_up, Qb, M_ROWS, NQK, QL, QL, QL, NQK);
    // 4) rope + scale + split -> Qz[z][s][192]
    q_post_kernel<<<(M_ROWS*NH_*(QK_/2) + 255)/256, 256>>>(Qb, freqs, Qzh, Qzl, scale);
    // 5) kvd = x @ Wkv_down^T + b
    mma_gemm<<<dim3((KVD_+127)/128, M_ROWS/128), 256>>>(
        xh, xl, Wkdh, Wkdl, bkv_down, kvd, M_ROWS, KVD_, DIM_, DIM_, DIM_, KVD_);
    // 6) kv_lat = rmsnorm -> split ; K rope part -> Kf cols 128..191
    rmsnorm_split_kernel<<<M_ROWS, 256>>>(kvd, kv_norm, klh, kll, KVL, KVD_);
    k_rope_kernel<<<(M_ROWS*(ROPE_D/2) + 255)/256, 256>>>(kvd, freqs, Kfh, Kfl);
    // 7) KV = kv_lat @ Wkv_up^T + b
    mma_gemm<<<dim3(NKV/128, M_ROWS/128), 256>>>(
        klh, kll, Wkuh, Wkul, bkv_up, KVb, M_ROWS, NKV, KVL, KVL, KVL, NKV);
    // 8) unpack K_nope + V -> split flash layouts
    kv_post_kernel<<<(int)(((long long)M_ROWS*NH_*(NOPE_+VDIM_) + 255)/256), 256>>>(
        KVb, Kfh, Kfl, Vzh, Vzl);
    // 9) fused flash attention -> Oh/Ol [m][2048]
    flash_kernel<<<dim3(16, BATCH*NH_), 256, FLASH_SMEM>>>(
        Qzh, Qzl, Kfh, Kfl, Vzh, Vzl, Oh, Ol);
    // 10) out = O @ Wo^T + b
    mma_gemm<<<dim3(DIM_/128, M_ROWS/128), 256>>>(
        Oh, Ol, Woh, Wol, bo, out, M_ROWS, DIM_, NH_*VDIM_, NH_*VDIM_, NH_*VDIM_, DIM_);
}